// round 9
// baseline (speedup 1.0000x reference)
#include <cuda_runtime.h>
#include <cuda_fp16.h>
#include <cstdint>

// Problem dims (fixed): X:(B,N), boundaries:(N,K+1), weight:(N,K,E), bias:(N,E)
#define BDIM 4096
#define NDIM 64
#define KDIM 128
#define EDIM 512
#define EPS_F 1e-8f
#define NCHUNK 16
#define CHK (KDIM / NCHUNK)          // 8

// Prefix table T[n][k][e] (fp16): T[n][k][e] = bias[n][e] + sum_{j<k} w[n][j][e]
// out[b][n][e] = relu( lerp(T[n][bidx], T[n][bidx+1], frac) )
__device__ __half g_T16[(size_t)NDIM * (KDIM + 1) * EDIM];
// Per-(b,n) (frac, bidx), indexed b*N+n.
__device__ float2 g_SF[(size_t)BDIM * NDIM];
// Chunk sums: S[n][c][eg] as float4 (64*16*128 = 2MB)
__device__ float4 g_S4[(size_t)NDIM * NCHUNK * (EDIM / 4)];

#define CHUNK_THREADS (NDIM * NCHUNK * (EDIM / 4))     // 131072
#define CHUNK_BLOCKS  (CHUNK_THREADS / 256)            // 512
#define SEARCH_BLOCKS ((BDIM * NDIM) / (256 * 2))      // 512 (ILP-2)

__device__ __forceinline__ uint2 pack4half(float4 v) {
    __half2 lo2 = __floats2half2_rn(v.x, v.y);
    __half2 hi2 = __floats2half2_rn(v.z, v.w);
    uint2 pk;
    pk.x = *(unsigned*)&lo2;
    pk.y = *(unsigned*)&hi2;
    return pk;
}

__device__ __forceinline__ float2 search_one(const float* bn, float x) {
    int lo = 0, len = KDIM - 1;
    while (len > 0) {
        int half = len >> 1;
        bool pred = __ldg(&bn[1 + lo + half]) < x;
        lo  += pred ? (half + 1) : 0;
        len  = pred ? (len - half - 1) : half;
    }
    const float s  = __ldg(&bn[lo]);
    const float eb = __ldg(&bn[lo + 1]);
    return make_float2((x - s) / (eb - s + EPS_F), __int_as_float(lo));
}

// ---------------------------------------------------------------------------
// Setup A (fused):
//  blocks [0,512): chunk sums S[n][c][eg] = sum of 8 k's, float4 (MLP-8).
//  blocks [512,1024): TWO interleaved binary searches per thread (ILP-2),
//    covering all (b,n) -> g_SF.
// ---------------------------------------------------------------------------
__global__ void setup_a_kernel(const float* __restrict__ X,
                               const float* __restrict__ bnd,
                               const float* __restrict__ weight) {
    if (blockIdx.x < CHUNK_BLOCKS) {
        int t = blockIdx.x * blockDim.x + threadIdx.x;
        int eg  = t & 127;            // e = 4*eg
        int tmp = t >> 7;             // n*16 + c
        int c   = tmp & 15;
        int n   = tmp >> 4;

        const float4* wp = (const float4*)(weight + (size_t)n * KDIM * EDIM)
                         + (size_t)(c * CHK) * (EDIM / 4) + eg;
        float4 s = make_float4(0.f, 0.f, 0.f, 0.f);
#pragma unroll
        for (int j = 0; j < CHK; j++) {
            float4 w = wp[(size_t)j * (EDIM / 4)];
            s.x += w.x; s.y += w.y; s.z += w.z; s.w += w.w;
        }
        g_S4[t] = s;
    } else {
        int i0 = (blockIdx.x - CHUNK_BLOCKS) * blockDim.x + threadIdx.x;
        int i1 = i0 + (BDIM * NDIM) / 2;                  // second pair

        const float x0 = X[i0];
        const float x1 = X[i1];
        const float* bn0 = bnd + (size_t)(i0 & (NDIM - 1)) * (KDIM + 1);
        const float* bn1 = bnd + (size_t)(i1 & (NDIM - 1)) * (KDIM + 1);

        // two interleaved independent binary searches
        int lo0 = 0, lo1 = 0, len = KDIM - 1;
        while (len > 0) {
            int half = len >> 1;
            bool p0 = __ldg(&bn0[1 + lo0 + half]) < x0;
            bool p1 = __ldg(&bn1[1 + lo1 + half]) < x1;
            lo0 += p0 ? (half + 1) : 0;
            lo1 += p1 ? (half + 1) : 0;
            // same len evolution only if both take same branch — NOT guaranteed.
            // So run classic per-chain lengths instead:
            len = half;                 // len halves identically: 127->63->31->15->7->3->1->0
            lo0 += 0; lo1 += 0;
        }
        // NOTE: uniform-len bisection above requires len = 2^m - 1 pattern:
        // 127 -> 63 -> 31 -> 15 -> 7 -> 3 -> 1 -> 0, with lo += pred?(half+1):0
        // This is the standard branchless lower_bound for len=127; valid since
        // both chains share the same len sequence.
        const float s0  = __ldg(&bn0[lo0]);
        const float e0  = __ldg(&bn0[lo0 + 1]);
        const float s1  = __ldg(&bn1[lo1]);
        const float e1  = __ldg(&bn1[lo1 + 1]);
        g_SF[i0] = make_float2((x0 - s0) / (e0 - s0 + EPS_F), __int_as_float(lo0));
        g_SF[i1] = make_float2((x1 - s1) / (e1 - s1 + EPS_F), __int_as_float(lo1));
    }
}

// ---------------------------------------------------------------------------
// Setup B: scan. Thread = (n, c, eg): base = bias + sum of chunk sums < c
// (L2-hot float4 loads, MLP), then 8-step scan storing packed 4-half uint2.
// ---------------------------------------------------------------------------
__global__ void setup_b_kernel(const float* __restrict__ weight,
                               const float* __restrict__ bias) {
    int t = blockIdx.x * blockDim.x + threadIdx.x;
    int eg  = t & 127;
    int tmp = t >> 7;
    int c   = tmp & 15;
    int n   = tmp >> 4;

    float4 acc = ((const float4*)(bias + (size_t)n * EDIM))[eg];
    const float4* Sp = g_S4 + ((size_t)n * NCHUNK) * (EDIM / 4) + eg;
#pragma unroll
    for (int cc = 0; cc < NCHUNK - 1; cc++) {
        if (cc < c) {
            float4 s = Sp[(size_t)cc * (EDIM / 4)];
            acc.x += s.x; acc.y += s.y; acc.z += s.z; acc.w += s.w;
        }
    }

    const int k0 = c * CHK;
    const float4* wp = (const float4*)(weight + (size_t)n * KDIM * EDIM)
                     + (size_t)k0 * (EDIM / 4) + eg;
    uint2* Tp = (uint2*)g_T16 + ((size_t)n * (KDIM + 1) + k0) * (EDIM / 4) + eg;

#pragma unroll
    for (int j = 0; j < CHK; j++) {
        Tp[(size_t)j * (EDIM / 4)] = pack4half(acc);
        float4 w = wp[(size_t)j * (EDIM / 4)];
        acc.x += w.x; acc.y += w.y; acc.z += w.z; acc.w += w.w;
    }
    if (c == NCHUNK - 1)
        Tp[(size_t)CHK * (EDIM / 4)] = pack4half(acc);
}

// ---------------------------------------------------------------------------
// Gather (proven 86.4us config): one warp per (b,n). Front-batched table
// LDG.128s, fp32 lerp, STS to this warp's 2KB SMEM slot, one per-warp
// cp.async.bulk TMA store. __syncwarp only — no block barrier.
// ---------------------------------------------------------------------------
__global__ void gather_kernel(float* __restrict__ out) {
    __shared__ float4 sm[8][EDIM / 4];                 // 8 x 2KB = 16KB

    const int lane = threadIdx.x & 31;
    const int warp = threadIdx.x >> 5;
    const int n = blockIdx.y;
    const int b = blockIdx.x * 8 + warp;

    const float2 sf = __ldg(&g_SF[(size_t)b * NDIM + n]);
    const float frac = sf.x;
    const int   lo   = __float_as_int(sf.y);

    const uint4* T0 = (const uint4*)(g_T16 + ((size_t)n * (KDIM + 1) + lo) * EDIM);
    const uint4* T1 = T0 + (EDIM / 8);

    uint4 a0 = __ldg(&T0[lane]);
    uint4 c0 = __ldg(&T1[lane]);
    uint4 a1 = __ldg(&T0[lane + 32]);
    uint4 c1 = __ldg(&T1[lane + 32]);

#pragma unroll
    for (int j = 0; j < 2; j++) {
        const uint4& a  = j ? a1 : a0;
        const uint4& cc = j ? c1 : c0;
        const unsigned* ap = &a.x;
        const unsigned* cp = &cc.x;
        float4 r0, r1;
#pragma unroll
        for (int q = 0; q < 4; q++) {
            float2 av = __half22float2(*(const __half2*)&ap[q]);
            float2 cv = __half22float2(*(const __half2*)&cp[q]);
            float v0 = fmaxf(fmaf(frac, cv.x - av.x, av.x), 0.0f);
            float v1 = fmaxf(fmaf(frac, cv.y - av.y, av.y), 0.0f);
            if (q == 0)      { r0.x = v0; r0.y = v1; }
            else if (q == 1) { r0.z = v0; r0.w = v1; }
            else if (q == 2) { r1.x = v0; r1.y = v1; }
            else             { r1.z = v0; r1.w = v1; }
        }
        const int i = lane + 32 * j;
        sm[warp][2 * i]     = r0;
        sm[warp][2 * i + 1] = r1;
    }

    __syncwarp();

    if (lane == 0) {
        float* gdst = out + ((size_t)b * NDIM + n) * EDIM;
        uint32_t saddr;
        asm("{ .reg .u64 t; cvta.to.shared.u64 t, %1; cvt.u32.u64 %0, t; }"
            : "=r"(saddr) : "l"(&sm[warp][0]));
        asm volatile("fence.proxy.async.shared::cta;" ::: "memory");
        asm volatile(
            "cp.async.bulk.global.shared::cta.bulk_group [%0], [%1], %2;"
            :: "l"(gdst), "r"(saddr), "r"((int)(EDIM * 4)) : "memory");
        asm volatile("cp.async.bulk.commit_group;" ::: "memory");
        asm volatile("cp.async.bulk.wait_group 0;" ::: "memory");
    }
}

extern "C" void kernel_launch(void* const* d_in, const int* in_sizes, int n_in,
                              void* d_out, int out_size) {
    const float* X      = (const float*)d_in[0];   // (B, N)
    const float* bnd    = (const float*)d_in[1];   // (N, K+1)
    const float* weight = (const float*)d_in[2];   // (N, K, E)
    const float* bias   = (const float*)d_in[3];   // (N, E)
    float* out = (float*)d_out;                    // (B, N, E)

    setup_a_kernel<<<CHUNK_BLOCKS + SEARCH_BLOCKS, 256>>>(X, bnd, weight);
    setup_b_kernel<<<CHUNK_BLOCKS, 256>>>(weight, bias);

    dim3 grid(BDIM / 8, NDIM);
    gather_kernel<<<grid, 256>>>(out);
}